// round 7
// baseline (speedup 1.0000x reference)
#include <cuda_runtime.h>
#include <cstdint>

#define SCALE_F 0.08838834764831845f

// ---------------- smem byte offsets ----------------
#define QT_H   0        // Q hi: 32 rows x 256B (swizzled)
#define QT_L   8192     // Q lo
#define P_HI   16384    // P hi: 32 h x 512B (swizzled)
#define P_LO   32768    // P lo
#define REDM   49152    // 8 warps x 32 f32 max partials
#define REDS   50176    // 8 warps x 32 f32 sum partials
#define SIDX   51200    // 256 int32
#define SMEM_BYTES 52224

// ---------------- helpers ----------------
static __device__ __forceinline__ uint32_t smem_u32(const void* p) {
    uint32_t a;
    asm("{ .reg .u64 t; cvta.to.shared.u64 t, %1; cvt.u32.u64 %0, t; }" : "=r"(a) : "l"(p));
    return a;
}
static __device__ __forceinline__ void ldm4(uint32_t* r, uint32_t addr) {
    asm volatile("ldmatrix.sync.aligned.m8n8.x4.shared.b16 {%0,%1,%2,%3}, [%4];"
                 : "=r"(r[0]), "=r"(r[1]), "=r"(r[2]), "=r"(r[3]) : "r"(addr));
}
static __device__ __forceinline__ void mma16816(float* c, const uint32_t* a,
                                                uint32_t b0, uint32_t b1) {
    asm volatile("mma.sync.aligned.m16n8k16.row.col.f32.bf16.bf16.f32 "
                 "{%0,%1,%2,%3}, {%4,%5,%6,%7}, {%8,%9}, {%0,%1,%2,%3};"
                 : "+f"(c[0]), "+f"(c[1]), "+f"(c[2]), "+f"(c[3])
                 : "r"(a[0]), "r"(a[1]), "r"(a[2]), "r"(a[3]), "r"(b0), "r"(b1));
}
// scalar truncation split
static __device__ __forceinline__ void sp(float x, unsigned short& h, unsigned short& l) {
    unsigned xb = __float_as_uint(x);
    h = (unsigned short)(xb >> 16);
    float r = x - __uint_as_float(xb & 0xFFFF0000u);
    asm("cvt.rn.bf16.f32 %0, %1;" : "=h"(l) : "f"(r));
}
// pair split: H = (bf16t(x0) lo-half, bf16t(x1) hi-half); L = residual pair
static __device__ __forceinline__ void sp2(float x0, float x1, uint32_t& H, uint32_t& L) {
    unsigned u0 = __float_as_uint(x0), u1 = __float_as_uint(x1);
    asm("prmt.b32 %0, %1, %2, 0x7632;" : "=r"(H) : "r"(u0), "r"(u1));
    float r0 = x0 - __uint_as_float(u0 & 0xFFFF0000u);
    float r1 = x1 - __uint_as_float(u1 & 0xFFFF0000u);
    asm("cvt.rn.bf16x2.f32 %0, %1, %2;" : "=r"(L) : "f"(r1), "f"(r0));
}

__global__ void __launch_bounds__(256, 2)
sparse_attn_v7(const float* __restrict__ q, const float* __restrict__ kv,
               const float* __restrict__ sink, const int* __restrict__ topk,
               float* __restrict__ out) {
    extern __shared__ __align__(1024) unsigned char smem[];
    const uint32_t sb = smem_u32(smem);
    const int tid = threadIdx.x, wid = tid >> 5, lid = tid & 31;
    const int l15 = lid & 15, lh = lid >> 4;
    const int sq = blockIdx.x;
    int*   sidx = (int*)(smem + SIDX);
    float* redm = (float*)(smem + REDM);
    float* reds = (float*)(smem + REDS);

    // ---- init: indices + Q convert (scale + split, swizzled) ----
    sidx[tid] = __ldg(topk + (long)sq * 256 + tid);
    const float* qg = q + (long)sq * 4096;
#pragma unroll
    for (int it = 0; it < 2; it++) {
        int f = tid + it * 256;
        int r = f >> 4, ch = f & 15;
        const float* src = qg + r * 128 + ch * 8;
        float4 a = *(const float4*)src;
        float4 b = *(const float4*)(src + 4);
        uint4 H, L;
        sp2(a.x * SCALE_F, a.y * SCALE_F, H.x, L.x);
        sp2(a.z * SCALE_F, a.w * SCALE_F, H.y, L.y);
        sp2(b.x * SCALE_F, b.y * SCALE_F, H.z, L.z);
        sp2(b.z * SCALE_F, b.w * SCALE_F, H.w, L.w);
        uint32_t o = r * 256 + ((ch ^ (r & 7)) << 4);
        *(uint4*)(smem + QT_H + o) = H;
        *(uint4*)(smem + QT_L + o) = L;
    }
    __syncthreads();

    // ================= Phase A: scores (warp owns 32 k-rows, M32xN32) ====
    const int rbase = wid * 32 + (lid >> 2);
    const int cof = (lid & 3) * 2;
    const float* kp[4];
#pragma unroll
    for (int m = 0; m < 4; m++)
        kp[m] = kv + (long)sidx[rbase + 8 * m] * 256 + cof;

    float sc[32];
#pragma unroll
    for (int t = 0; t < 32; t++) sc[t] = 0.f;

    float2 v[8];
#pragma unroll
    for (int m = 0; m < 4; m++) {
        v[2 * m]     = *(const float2*)(kp[m]);
        v[2 * m + 1] = *(const float2*)(kp[m] + 8);
    }
#pragma unroll
    for (int s = 0; s < 8; s++) {
        float2 vn[8];
        if (s < 7) {
#pragma unroll
            for (int m = 0; m < 4; m++) {
                vn[2 * m]     = *(const float2*)(kp[m] + 16 * (s + 1));
                vn[2 * m + 1] = *(const float2*)(kp[m] + 16 * (s + 1) + 8);
            }
        }
        uint32_t aH[2][4], aL[2][4];
#pragma unroll
        for (int t = 0; t < 2; t++) {
            sp2(v[4 * t + 0].x, v[4 * t + 0].y, aH[t][0], aL[t][0]); // (r,     k..k+1)
            sp2(v[4 * t + 2].x, v[4 * t + 2].y, aH[t][1], aL[t][1]); // (r+8,   k..k+1)
            sp2(v[4 * t + 1].x, v[4 * t + 1].y, aH[t][2], aL[t][2]); // (r,     k+8..9)
            sp2(v[4 * t + 3].x, v[4 * t + 3].y, aH[t][3], aL[t][3]); // (r+8,   k+8..9)
        }
        int ch = 2 * s + lh;
        uint32_t q0 = l15 * 256 + ((ch ^ (l15 & 7)) << 4);
        uint32_t bH0[4], bH1[4], bL0[4], bL1[4];
        ldm4(bH0, sb + QT_H + q0);
        ldm4(bH1, sb + QT_H + q0 + 4096);
        ldm4(bL0, sb + QT_L + q0);
        ldm4(bL1, sb + QT_L + q0 + 4096);
#pragma unroll
        for (int t = 0; t < 2; t++) {
            float* c = sc + 16 * t;
            mma16816(c + 0,  aH[t], bH0[0], bH0[2]);
            mma16816(c + 4,  aH[t], bH0[1], bH0[3]);
            mma16816(c + 8,  aH[t], bH1[0], bH1[2]);
            mma16816(c + 12, aH[t], bH1[1], bH1[3]);
            mma16816(c + 0,  aH[t], bL0[0], bL0[2]);
            mma16816(c + 4,  aH[t], bL0[1], bL0[3]);
            mma16816(c + 8,  aH[t], bL1[0], bL1[2]);
            mma16816(c + 12, aH[t], bL1[1], bL1[3]);
            mma16816(c + 0,  aL[t], bH0[0], bH0[2]);
            mma16816(c + 4,  aL[t], bH0[1], bH0[3]);
            mma16816(c + 8,  aL[t], bH1[0], bH1[2]);
            mma16816(c + 12, aL[t], bH1[1], bH1[3]);
        }
        if (s < 7) {
#pragma unroll
            for (int i = 0; i < 8; i++) v[i] = vn[i];
        }
    }

    // ================= softmax (regs -> P tiles) ========================
    {
        float mx[8];
#pragma unroll
        for (int jj = 0; jj < 8; jj++) mx[jj] = -1e30f;
#pragma unroll
        for (int t = 0; t < 2; t++)
#pragma unroll
            for (int j = 0; j < 4; j++) {
                float* f = sc + 16 * t + 4 * j;
                mx[2 * j + 0] = fmaxf(mx[2 * j + 0], fmaxf(f[0], f[2]));
                mx[2 * j + 1] = fmaxf(mx[2 * j + 1], fmaxf(f[1], f[3]));
            }
#pragma unroll
        for (int off = 4; off < 32; off <<= 1)
#pragma unroll
            for (int jj = 0; jj < 8; jj++)
                mx[jj] = fmaxf(mx[jj], __shfl_xor_sync(0xffffffffu, mx[jj], off));
        if (lid < 4) {
#pragma unroll
            for (int jj = 0; jj < 8; jj++)
                redm[wid * 32 + 8 * (jj >> 1) + 2 * lid + (jj & 1)] = mx[jj];
        }
        __syncthreads();

        float mfin[8];
#pragma unroll
        for (int jj = 0; jj < 8; jj++) {
            int h = 8 * (jj >> 1) + 2 * (lid & 3) + (jj & 1);
            float m = __ldg(sink + h);
#pragma unroll
            for (int w = 0; w < 8; w++) m = fmaxf(m, redm[w * 32 + h]);
            mfin[jj] = m;
        }
        float sm[8];
#pragma unroll
        for (int jj = 0; jj < 8; jj++) sm[jj] = 0.f;
#pragma unroll
        for (int t = 0; t < 2; t++)
#pragma unroll
            for (int j = 0; j < 4; j++) {
                int k0 = rbase + 16 * t;       // global k of c0/c1; c2/c3 at k0+8
                int h0 = 8 * j + 2 * (lid & 3);
                float e0 = __expf(sc[16 * t + 4 * j + 0] - mfin[2 * j + 0]);
                float e1 = __expf(sc[16 * t + 4 * j + 1] - mfin[2 * j + 1]);
                float e2 = __expf(sc[16 * t + 4 * j + 2] - mfin[2 * j + 0]);
                float e3 = __expf(sc[16 * t + 4 * j + 3] - mfin[2 * j + 1]);
                sm[2 * j + 0] += e0 + e2;
                sm[2 * j + 1] += e1 + e3;
                unsigned short ph, pl; uint32_t o;
                sp(e0, ph, pl);
                o = h0 * 512 + (((k0 >> 3) ^ (h0 & 7)) << 4) + ((k0 & 7) << 1);
                *(unsigned short*)(smem + P_HI + o) = ph;
                *(unsigned short*)(smem + P_LO + o) = pl;
                sp(e1, ph, pl);
                o = (h0 + 1) * 512 + (((k0 >> 3) ^ ((h0 + 1) & 7)) << 4) + ((k0 & 7) << 1);
                *(unsigned short*)(smem + P_HI + o) = ph;
                *(unsigned short*)(smem + P_LO + o) = pl;
                int k2 = k0 + 8;
                sp(e2, ph, pl);
                o = h0 * 512 + (((k2 >> 3) ^ (h0 & 7)) << 4) + ((k2 & 7) << 1);
                *(unsigned short*)(smem + P_HI + o) = ph;
                *(unsigned short*)(smem + P_LO + o) = pl;
                sp(e3, ph, pl);
                o = (h0 + 1) * 512 + (((k2 >> 3) ^ ((h0 + 1) & 7)) << 4) + ((k2 & 7) << 1);
                *(unsigned short*)(smem + P_HI + o) = ph;
                *(unsigned short*)(smem + P_LO + o) = pl;
            }
#pragma unroll
        for (int off = 4; off < 32; off <<= 1)
#pragma unroll
            for (int jj = 0; jj < 8; jj++)
                sm[jj] += __shfl_xor_sync(0xffffffffu, sm[jj], off);
        if (lid < 4) {
#pragma unroll
            for (int jj = 0; jj < 8; jj++)
                reds[wid * 32 + 8 * (jj >> 1) + 2 * lid + (jj & 1)] = sm[jj];
        }
        __syncthreads();   // P + reds ready for all warps
    }

    // ================= Phase C: out = P . V (warp = h-half x d-quarter) ==
    const int hg = wid & 1, dg = wid >> 1;
    const int hr = hg * 16 + l15;
    const float* vb = kv + 128 + dg * 32 + (lid >> 2);   // + id*256 per k-row
    const int kq = (lid & 3) * 2;

    float oacc[16];
#pragma unroll
    for (int t = 0; t < 16; t++) oacc[t] = 0.f;

    float vv[16];
    {
        const float* p0 = vb + (long)sidx[kq] * 256;
        const float* p1 = vb + (long)sidx[kq + 1] * 256;
        const float* p2 = vb + (long)sidx[kq + 8] * 256;
        const float* p3 = vb + (long)sidx[kq + 9] * 256;
#pragma unroll
        for (int j = 0; j < 4; j++) {
            vv[4 * j + 0] = p0[8 * j]; vv[4 * j + 1] = p1[8 * j];
            vv[4 * j + 2] = p2[8 * j]; vv[4 * j + 3] = p3[8 * j];
        }
    }
#pragma unroll
    for (int s = 0; s < 16; s++) {
        float vn[16];
        if (s < 15) {
            int kb = 16 * (s + 1) + kq;
            const float* p0 = vb + (long)sidx[kb] * 256;
            const float* p1 = vb + (long)sidx[kb + 1] * 256;
            const float* p2 = vb + (long)sidx[kb + 8] * 256;
            const float* p3 = vb + (long)sidx[kb + 9] * 256;
#pragma unroll
            for (int j = 0; j < 4; j++) {
                vn[4 * j + 0] = p0[8 * j]; vn[4 * j + 1] = p1[8 * j];
                vn[4 * j + 2] = p2[8 * j]; vn[4 * j + 3] = p3[8 * j];
            }
        }
        uint32_t aH[4], aL[4];
        uint32_t po = hr * 512 + (((2 * s + lh) ^ (hr & 7)) << 4);
        ldm4(aH, sb + P_HI + po);
        ldm4(aL, sb + P_LO + po);
#pragma unroll
        for (int j = 0; j < 4; j++) {
            uint32_t bH0, bH1, bL0, bL1;
            sp2(vv[4 * j + 0], vv[4 * j + 1], bH0, bL0);
            sp2(vv[4 * j + 2], vv[4 * j + 3], bH1, bL1);
            mma16816(oacc + 4 * j, aH, bH0, bH1);
            mma16816(oacc + 4 * j, aH, bL0, bL1);
            mma16816(oacc + 4 * j, aL, bH0, bH1);
        }
        if (s < 15) {
#pragma unroll
            for (int i = 0; i < 16; i++) vv[i] = vn[i];
        }
    }

    // ---- epilogue: per-warp inverse-denominator + store ----
    {
        const int h0e = hg * 16 + (lid >> 2);
        float iv[2];
#pragma unroll
        for (int i = 0; i < 2; i++) {
            int h = h0e + 8 * i;
            float sk = __ldg(sink + h);
            float m = sk;
#pragma unroll
            for (int w = 0; w < 8; w++) m = fmaxf(m, redm[w * 32 + h]);
            float den = __expf(sk - m);
#pragma unroll
            for (int w = 0; w < 8; w++) den += reds[w * 32 + h];
            iv[i] = 1.f / den;
        }
        float* op = out + (long)sq * 4096;
#pragma unroll
        for (int j = 0; j < 4; j++) {
            int d = dg * 32 + 8 * j + 2 * (lid & 3);
            *(float2*)(op + h0e * 128 + d) =
                make_float2(oacc[4 * j + 0] * iv[0], oacc[4 * j + 1] * iv[0]);
            *(float2*)(op + (h0e + 8) * 128 + d) =
                make_float2(oacc[4 * j + 2] * iv[1], oacc[4 * j + 3] * iv[1]);
        }
    }
}

extern "C" void kernel_launch(void* const* d_in, const int* in_sizes, int n_in,
                              void* d_out, int out_size) {
    (void)in_sizes; (void)n_in; (void)out_size;
    const float* q    = (const float*)d_in[0];
    const float* kv   = (const float*)d_in[1];
    const float* sink = (const float*)d_in[2];
    const int*   topk = (const int*)d_in[3];
    float* out = (float*)d_out;

    cudaFuncSetAttribute(sparse_attn_v7,
                         cudaFuncAttributeMaxDynamicSharedMemorySize, SMEM_BYTES);
    sparse_attn_v7<<<2048, 256, SMEM_BYTES>>>(q, kv, sink, topk, out);
}

// round 8
// speedup vs baseline: 1.2044x; 1.2044x over previous
#include <cuda_runtime.h>
#include <cstdint>

#define SCALE_F 0.08838834764831845f

// ---------------- smem byte offsets ----------------
#define KBH(b) ((b) * 32768)
#define KBL(b) ((b) * 32768 + 16384)
#define QT_H   65536     // Q hi: 32 rows x 256B
#define QT_L   73728     // Q lo
#define P_LO   65536     // P lo aliases QT (Q dead by softmax); 256 k x 64B
#define P_HI   81920     // P hi: 256 k x 64B
#define REDM   98304
#define REDS   98816
#define INVV   99328
#define SIDX   99456
#define SMEM_BYTES 100480

// ---------------- helpers ----------------
static __device__ __forceinline__ uint32_t smem_u32(const void* p) {
    uint32_t a;
    asm("{ .reg .u64 t; cvta.to.shared.u64 t, %1; cvt.u32.u64 %0, t; }" : "=r"(a) : "l"(p));
    return a;
}
static __device__ __forceinline__ void ldm4(uint32_t* r, uint32_t addr) {
    asm volatile("ldmatrix.sync.aligned.m8n8.x4.shared.b16 {%0,%1,%2,%3}, [%4];"
                 : "=r"(r[0]), "=r"(r[1]), "=r"(r[2]), "=r"(r[3]) : "r"(addr));
}
static __device__ __forceinline__ void ldm4t(uint32_t* r, uint32_t addr) {
    asm volatile("ldmatrix.sync.aligned.m8n8.x4.trans.shared.b16 {%0,%1,%2,%3}, [%4];"
                 : "=r"(r[0]), "=r"(r[1]), "=r"(r[2]), "=r"(r[3]) : "r"(addr));
}
static __device__ __forceinline__ void mma16816(float* c, const uint32_t* a,
                                                uint32_t b0, uint32_t b1) {
    asm volatile("mma.sync.aligned.m16n8k16.row.col.f32.bf16.bf16.f32 "
                 "{%0,%1,%2,%3}, {%4,%5,%6,%7}, {%8,%9}, {%0,%1,%2,%3};"
                 : "+f"(c[0]), "+f"(c[1]), "+f"(c[2]), "+f"(c[3])
                 : "r"(a[0]), "r"(a[1]), "r"(a[2]), "r"(a[3]), "r"(b0), "r"(b1));
}
// pair split: H = packed (bf16t(x0), bf16t(x1)); L = packed residuals
static __device__ __forceinline__ void sp2(float x0, float x1, uint32_t& H, uint32_t& L) {
    unsigned u0 = __float_as_uint(x0), u1 = __float_as_uint(x1);
    asm("prmt.b32 %0, %1, %2, 0x7632;" : "=r"(H) : "r"(u0), "r"(u1));
    float r0 = x0 - __uint_as_float(u0 & 0xFFFF0000u);
    float r1 = x1 - __uint_as_float(u1 & 0xFFFF0000u);
    asm("cvt.rn.bf16x2.f32 %0, %1, %2;" : "=r"(L) : "f"(r1), "f"(r0));
}
static __device__ __forceinline__ void cv8t(const float* f, uint4& H, uint4& L) {
    sp2(f[0], f[1], ((uint32_t*)&H)[0], ((uint32_t*)&L)[0]);
    sp2(f[2], f[3], ((uint32_t*)&H)[1], ((uint32_t*)&L)[1]);
    sp2(f[4], f[5], ((uint32_t*)&H)[2], ((uint32_t*)&L)[2]);
    sp2(f[6], f[7], ((uint32_t*)&H)[3], ((uint32_t*)&L)[3]);
}
// k-major P byte offset for (k, h-chunk hc in 0..3): row 64B, XOR swizzle
static __device__ __forceinline__ uint32_t poff(int k, int hc) {
    return (uint32_t)(k * 64 + ((hc ^ ((k >> 1) & 3)) << 4));
}

// producer: gather + split-convert one 64-row half into buffer buf
static __device__ __forceinline__ void prod_half(
    unsigned char* smem, const float* kv, const int* sidx,
    int base, int hc, int buf, int pt) {
    const int ch = pt & 15;
    const int r0 = pt >> 4;
#pragma unroll
    for (int bb = 0; bb < 4; bb++) {
        float v[2][8];
        int r[2];
#pragma unroll
        for (int it = 0; it < 2; it++) {
            r[it] = r0 + (bb * 2 + it) * 8;
            int id = sidx[hc * 64 + r[it]];
            const float* src = kv + (long)id * 256 + base + ch * 8;
            *(float4*)(v[it]) = *(const float4*)(src);
            *(float4*)(v[it] + 4) = *(const float4*)(src + 4);
        }
#pragma unroll
        for (int it = 0; it < 2; it++) {
            uint4 H, L; cv8t(v[it], H, L);
            uint32_t o = r[it] * 256 + ((ch ^ (r[it] & 7)) << 4);
            *(uint4*)(smem + KBH(buf) + o) = H;
            *(uint4*)(smem + KBL(buf) + o) = L;
        }
    }
}

// consumer Phase A: 64-row half-chunk, warp tile M16 x N32
static __device__ __forceinline__ void mma_A(
    uint32_t sb, int buf, float* scc, int cw, int l15, int lh) {
    const int arow = cw * 16 + l15;
    const int qrow0 = l15, qrow1 = 16 + l15;
#pragma unroll
    for (int s = 0; s < 8; s++) {
        int ch = 2 * s + lh;
        uint32_t ao = arow * 256 + ((ch ^ (arow & 7)) << 4);
        uint32_t q0 = qrow0 * 256 + ((ch ^ (qrow0 & 7)) << 4);
        uint32_t q1 = qrow1 * 256 + ((ch ^ (qrow1 & 7)) << 4);
        uint32_t aH[4], aL[4], bH0[4], bH1[4], bL0[4], bL1[4];
        ldm4(aH, sb + KBH(buf) + ao);
        ldm4(aL, sb + KBL(buf) + ao);
        ldm4(bH0, sb + QT_H + q0);
        ldm4(bH1, sb + QT_H + q1);
        ldm4(bL0, sb + QT_L + q0);
        ldm4(bL1, sb + QT_L + q1);
        mma16816(scc + 0,  aH, bH0[0], bH0[2]);
        mma16816(scc + 4,  aH, bH0[1], bH0[3]);
        mma16816(scc + 8,  aH, bH1[0], bH1[2]);
        mma16816(scc + 12, aH, bH1[1], bH1[3]);
        mma16816(scc + 0,  aH, bL0[0], bL0[2]);
        mma16816(scc + 4,  aH, bL0[1], bL0[3]);
        mma16816(scc + 8,  aH, bL1[0], bL1[2]);
        mma16816(scc + 12, aH, bL1[1], bL1[3]);
        mma16816(scc + 0,  aL, bH0[0], bH0[2]);
        mma16816(scc + 4,  aL, bH0[1], bH0[3]);
        mma16816(scc + 8,  aL, bH1[0], bH1[2]);
        mma16816(scc + 12, aL, bH1[1], bH1[3]);
    }
}

// consumer Phase C: 64 V-rows in buf (global half hcl), warp tile M32h x N32d
// P is k-major; A-frags come from ldmatrix.trans.
static __device__ __forceinline__ void mma_C(
    uint32_t sb, int buf, int hcl, float* oacc, int cw, int l15, int lh, int lid) {
    // trans ldmatrix lane addressing (per 8-lane phase = one 8x8 source block)
    const int kl = (lid & 7) + ((lid >> 4) << 3);   // k offset within 16
    const int hcL = (lid >> 3) & 1;                 // chunk parity within pair
#pragma unroll
    for (int s = 0; s < 4; s++) {
        int kb = hcl * 64 + s * 16;
        int kk = kb + kl;
        uint32_t adr0 = poff(kk, hcL);        // h0-15
        uint32_t adr1 = poff(kk, 2 + hcL);    // h16-31
        uint32_t aH0[4], aH1[4], aL0[4], aL1[4];
        ldm4t(aH0, sb + P_HI + adr0);
        ldm4t(aH1, sb + P_HI + adr1);
        ldm4t(aL0, sb + P_LO + adr0);
        ldm4t(aL1, sb + P_LO + adr1);
        int vrow = s * 16 + l15;
        uint32_t vc0 = cw * 4 + lh, vc1 = vc0 + 2;
        uint32_t v0 = vrow * 256 + ((vc0 ^ (vrow & 7)) << 4);
        uint32_t v1 = vrow * 256 + ((vc1 ^ (vrow & 7)) << 4);
        uint32_t vH0[4], vH1[4], vL0[4], vL1[4];
        ldm4t(vH0, sb + KBH(buf) + v0);
        ldm4t(vH1, sb + KBH(buf) + v1);
        ldm4t(vL0, sb + KBL(buf) + v0);
        ldm4t(vL1, sb + KBL(buf) + v1);
        mma16816(oacc + 0,  aH0, vH0[0], vH0[1]);
        mma16816(oacc + 4,  aH0, vH0[2], vH0[3]);
        mma16816(oacc + 8,  aH0, vH1[0], vH1[1]);
        mma16816(oacc + 12, aH0, vH1[2], vH1[3]);
        mma16816(oacc + 16, aH1, vH0[0], vH0[1]);
        mma16816(oacc + 20, aH1, vH0[2], vH0[3]);
        mma16816(oacc + 24, aH1, vH1[0], vH1[1]);
        mma16816(oacc + 28, aH1, vH1[2], vH1[3]);
        mma16816(oacc + 0,  aH0, vL0[0], vL0[1]);
        mma16816(oacc + 4,  aH0, vL0[2], vL0[3]);
        mma16816(oacc + 8,  aH0, vL1[0], vL1[1]);
        mma16816(oacc + 12, aH0, vL1[2], vL1[3]);
        mma16816(oacc + 16, aH1, vL0[0], vL0[1]);
        mma16816(oacc + 20, aH1, vL0[2], vL0[3]);
        mma16816(oacc + 24, aH1, vL1[0], vL1[1]);
        mma16816(oacc + 28, aH1, vL1[2], vL1[3]);
        mma16816(oacc + 0,  aL0, vH0[0], vH0[1]);
        mma16816(oacc + 4,  aL0, vH0[2], vH0[3]);
        mma16816(oacc + 8,  aL0, vH1[0], vH1[1]);
        mma16816(oacc + 12, aL0, vH1[2], vH1[3]);
        mma16816(oacc + 16, aL1, vH0[0], vH0[1]);
        mma16816(oacc + 20, aL1, vH0[2], vH0[3]);
        mma16816(oacc + 24, aL1, vH1[0], vH1[1]);
        mma16816(oacc + 28, aL1, vH1[2], vH1[3]);
    }
}

__global__ void __launch_bounds__(256, 2)
sparse_attn_v8(const float* __restrict__ q, const float* __restrict__ kv,
               const float* __restrict__ sink, const int* __restrict__ topk,
               float* __restrict__ out) {
    extern __shared__ __align__(1024) unsigned char smem[];
    const uint32_t sb = smem_u32(smem);
    const int tid = threadIdx.x, wid = tid >> 5, lid = tid & 31;
    const int l15 = lid & 15, lh = lid >> 4;
    const int pt = tid & 127;
    const int cw = wid & 3;
    const bool cons = wid < 4;
    const int sq = blockIdx.x;
    float* redm = (float*)(smem + REDM);
    float* reds = (float*)(smem + REDS);
    float* invv = (float*)(smem + INVV);
    int*   sidx = (int*)(smem + SIDX);

    float sc[64];
    float oacc[32];

    // ---- s0: consumers convert Q; producers cache indices + K half0 ----
    if (cons) {
        const float* qg = q + (long)sq * 4096;
#pragma unroll
        for (int it = 0; it < 4; it++) {
            int f = pt + it * 128;
            int r = f >> 4, ch = f & 15;
            float v[8];
            *(float4*)(v) = *(const float4*)(qg + r * 128 + ch * 8);
            *(float4*)(v + 4) = *(const float4*)(qg + r * 128 + ch * 8 + 4);
#pragma unroll
            for (int i = 0; i < 8; i++) v[i] *= SCALE_F;
            uint4 H, L; cv8t(v, H, L);
            uint32_t o = r * 256 + ((ch ^ (r & 7)) << 4);
            *(uint4*)(smem + QT_H + o) = H;
            *(uint4*)(smem + QT_L + o) = L;
        }
#pragma unroll
        for (int t = 0; t < 64; t++) sc[t] = 0.f;
    } else {
        sidx[pt]       = __ldg(topk + (long)sq * 256 + pt);
        sidx[pt + 128] = __ldg(topk + (long)sq * 256 + 128 + pt);
        asm volatile("bar.sync 2, 128;" ::: "memory");
        prod_half(smem, kv, sidx, 0, 0, 0, pt);
    }
    __syncthreads();

    // ---- s1-s4: Phase A MMA pipeline ----
    if (cons) mma_A(sb, 0, sc + 0, cw, l15, lh);
    else      prod_half(smem, kv, sidx, 0, 1, 1, pt);
    __syncthreads();
    if (cons) mma_A(sb, 1, sc + 16, cw, l15, lh);
    else      prod_half(smem, kv, sidx, 0, 2, 0, pt);
    __syncthreads();
    if (cons) mma_A(sb, 0, sc + 32, cw, l15, lh);
    else      prod_half(smem, kv, sidx, 0, 3, 1, pt);
    __syncthreads();
    if (cons) mma_A(sb, 1, sc + 48, cw, l15, lh);
    else      prod_half(smem, kv, sidx, 128, 0, 0, pt);   // V half0 -> b0
    __syncthreads();

    // ---- s5: consumers softmax -> k-major P; producers V half1 ----
    if (cons) {
        float mx[8];
#pragma unroll
        for (int jj = 0; jj < 8; jj++) mx[jj] = -1e30f;
#pragma unroll
        for (int t = 0; t < 2; t++)
#pragma unroll
            for (int j = 0; j < 4; j++) {
                float* f = sc + 16 * (2 * t) + 4 * j;      // hc = 2t
                float* g = sc + 16 * (2 * t + 1) + 4 * j;  // hc = 2t+1
                mx[2 * j + 0] = fmaxf(mx[2 * j + 0],
                                      fmaxf(fmaxf(f[0], f[2]), fmaxf(g[0], g[2])));
                mx[2 * j + 1] = fmaxf(mx[2 * j + 1],
                                      fmaxf(fmaxf(f[1], f[3]), fmaxf(g[1], g[3])));
            }
#pragma unroll
        for (int off = 4; off < 32; off <<= 1)
#pragma unroll
            for (int jj = 0; jj < 8; jj++)
                mx[jj] = fmaxf(mx[jj], __shfl_xor_sync(0xffffffffu, mx[jj], off));
        if (lid < 4) {
#pragma unroll
            for (int jj = 0; jj < 8; jj++)
                redm[cw * 32 + 8 * (jj >> 1) + 2 * lid + (jj & 1)] = mx[jj];
        }
        asm volatile("bar.sync 1, 128;" ::: "memory");
        float mfin[8];
#pragma unroll
        for (int jj = 0; jj < 8; jj++) {
            int h = 8 * (jj >> 1) + 2 * (lid & 3) + (jj & 1);
            float m = __ldg(sink + h);
#pragma unroll
            for (int w = 0; w < 4; w++) m = fmaxf(m, redm[w * 32 + h]);
            mfin[jj] = m;
        }
        float sm[8];
#pragma unroll
        for (int jj = 0; jj < 8; jj++) sm[jj] = 0.f;
#pragma unroll
        for (int hc = 0; hc < 4; hc++)
#pragma unroll
            for (int j = 0; j < 4; j++) {
                int kb = hc * 64 + cw * 16 + (lid >> 2);
                float e0 = __expf(sc[hc * 16 + 4 * j + 0] - mfin[2 * j + 0]);
                float e1 = __expf(sc[hc * 16 + 4 * j + 1] - mfin[2 * j + 1]);
                float e2 = __expf(sc[hc * 16 + 4 * j + 2] - mfin[2 * j + 0]);
                float e3 = __expf(sc[hc * 16 + 4 * j + 3] - mfin[2 * j + 1]);
                sm[2 * j + 0] += e0 + e2;
                sm[2 * j + 1] += e1 + e3;
                uint32_t H01, L01, H23, L23;
                sp2(e0, e1, H01, L01);
                sp2(e2, e3, H23, L23);
                uint32_t o0 = poff(kb, j) + 4 * (lid & 3);
                uint32_t o2 = poff(kb + 8, j) + 4 * (lid & 3);
                *(uint32_t*)(smem + P_HI + o0) = H01;
                *(uint32_t*)(smem + P_LO + o0) = L01;
                *(uint32_t*)(smem + P_HI + o2) = H23;
                *(uint32_t*)(smem + P_LO + o2) = L23;
            }
#pragma unroll
        for (int off = 4; off < 32; off <<= 1)
#pragma unroll
            for (int jj = 0; jj < 8; jj++)
                sm[jj] += __shfl_xor_sync(0xffffffffu, sm[jj], off);
        if (lid < 4) {
#pragma unroll
            for (int jj = 0; jj < 8; jj++)
                reds[cw * 32 + 8 * (jj >> 1) + 2 * lid + (jj & 1)] = sm[jj];
        }
        asm volatile("bar.sync 1, 128;" ::: "memory");
        if (cw == 0) {
            int h = lid;
            float sk = __ldg(sink + h);
            float m = sk;
#pragma unroll
            for (int w = 0; w < 4; w++) m = fmaxf(m, redm[w * 32 + h]);
            float den = __expf(sk - m);
#pragma unroll
            for (int w = 0; w < 4; w++) den += reds[w * 32 + h];
            invv[h] = 1.f / den;
        }
#pragma unroll
        for (int t = 0; t < 32; t++) oacc[t] = 0.f;
    } else {
        prod_half(smem, kv, sidx, 128, 1, 1, pt);   // V half1 -> b1
    }
    __syncthreads();

    // ---- s6-s9: Phase C MMA pipeline ----
    if (cons) mma_C(sb, 0, 0, oacc, cw, l15, lh, lid);
    __syncthreads();
    if (cons) mma_C(sb, 1, 1, oacc, cw, l15, lh, lid);
    else      prod_half(smem, kv, sidx, 128, 2, 0, pt);   // V half2 -> b0
    __syncthreads();
    if (cons) mma_C(sb, 0, 2, oacc, cw, l15, lh, lid);
    else      prod_half(smem, kv, sidx, 128, 3, 1, pt);   // V half3 -> b1
    __syncthreads();
    if (cons) {
        mma_C(sb, 1, 3, oacc, cw, l15, lh, lid);
        float* op = out + (long)sq * 4096;
#pragma unroll
        for (int i = 0; i < 2; i++) {
            int h0 = 16 * i + (lid >> 2);
            float iv0 = invv[h0], iv1 = invv[h0 + 8];
#pragma unroll
            for (int j = 0; j < 4; j++) {
                int d = cw * 32 + 8 * j + 2 * (lid & 3);
                float* b = oacc + i * 16 + j * 4;
                *(float2*)(op + h0 * 128 + d) = make_float2(b[0] * iv0, b[1] * iv0);
                *(float2*)(op + (h0 + 8) * 128 + d) = make_float2(b[2] * iv1, b[3] * iv1);
            }
        }
    }
}

extern "C" void kernel_launch(void* const* d_in, const int* in_sizes, int n_in,
                              void* d_out, int out_size) {
    (void)in_sizes; (void)n_in; (void)out_size;
    const float* q    = (const float*)d_in[0];
    const float* kv   = (const float*)d_in[1];
    const float* sink = (const float*)d_in[2];
    const int*   topk = (const int*)d_in[3];
    float* out = (float*)d_out;

    cudaFuncSetAttribute(sparse_attn_v8,
                         cudaFuncAttributeMaxDynamicSharedMemorySize, SMEM_BYTES);
    sparse_attn_v8<<<2048, 256, SMEM_BYTES>>>(q, kv, sink, topk, out);
}

// round 9
// speedup vs baseline: 1.3142x; 1.0912x over previous
#include <cuda_runtime.h>
#include <cstdint>

#define SCALE_F 0.08838834764831845f

// ---------------- smem byte offsets ----------------
#define KBH(b) ((b) * 32768)
#define KBL(b) ((b) * 32768 + 16384)
#define QT_H   65536     // Q hi: 32 rows x 256B
#define QT_L   73728     // Q lo
#define P_LO   65536     // P lo aliases QT (Q dead by softmax); 256 k x 64B
#define P_HI   81920     // P hi: 256 k x 64B
#define REDM   98304
#define REDS   98816
#define INVV   99328
#define SIDX   99456
#define SMEM_BYTES 100480

// ---------------- helpers ----------------
static __device__ __forceinline__ uint32_t smem_u32(const void* p) {
    uint32_t a;
    asm("{ .reg .u64 t; cvta.to.shared.u64 t, %1; cvt.u32.u64 %0, t; }" : "=r"(a) : "l"(p));
    return a;
}
static __device__ __forceinline__ void ldm4(uint32_t* r, uint32_t addr) {
    asm volatile("ldmatrix.sync.aligned.m8n8.x4.shared.b16 {%0,%1,%2,%3}, [%4];"
                 : "=r"(r[0]), "=r"(r[1]), "=r"(r[2]), "=r"(r[3]) : "r"(addr));
}
static __device__ __forceinline__ void ldm4t(uint32_t* r, uint32_t addr) {
    asm volatile("ldmatrix.sync.aligned.m8n8.x4.trans.shared.b16 {%0,%1,%2,%3}, [%4];"
                 : "=r"(r[0]), "=r"(r[1]), "=r"(r[2]), "=r"(r[3]) : "r"(addr));
}
static __device__ __forceinline__ void mma16816(float* c, const uint32_t* a,
                                                uint32_t b0, uint32_t b1) {
    asm volatile("mma.sync.aligned.m16n8k16.row.col.f32.bf16.bf16.f32 "
                 "{%0,%1,%2,%3}, {%4,%5,%6,%7}, {%8,%9}, {%0,%1,%2,%3};"
                 : "+f"(c[0]), "+f"(c[1]), "+f"(c[2]), "+f"(c[3])
                 : "r"(a[0]), "r"(a[1]), "r"(a[2]), "r"(a[3]), "r"(b0), "r"(b1));
}
// pair split: H = packed (bf16t(x0), bf16t(x1)); L = packed residuals
static __device__ __forceinline__ void sp2(float x0, float x1, uint32_t& H, uint32_t& L) {
    unsigned u0 = __float_as_uint(x0), u1 = __float_as_uint(x1);
    asm("prmt.b32 %0, %1, %2, 0x7632;" : "=r"(H) : "r"(u0), "r"(u1));
    float r0 = x0 - __uint_as_float(u0 & 0xFFFF0000u);
    float r1 = x1 - __uint_as_float(u1 & 0xFFFF0000u);
    asm("cvt.rn.bf16x2.f32 %0, %1, %2;" : "=r"(L) : "f"(r1), "f"(r0));
}
// k-major P byte offset for (k, h-chunk hc in 0..3): row 64B, XOR swizzle
static __device__ __forceinline__ uint32_t poff(int k, int hc) {
    return (uint32_t)(k * 64 + ((hc ^ ((k >> 1) & 3)) << 4));
}

// producer: gather + split-convert one 64-row half into buffer buf.
// One row per warp-instruction: 32 contiguous lanes x 16B = full 512B row
// (4 L1 lines/row vs 8 with the old strided pattern).
static __device__ __forceinline__ void prod_half(
    unsigned char* smem, const float* kv, const int* sidx,
    int base, int hc, int buf, int wloc, int lid) {
    const int rb = wloc * 16;
#pragma unroll
    for (int bb = 0; bb < 4; bb++) {
        float4 v[4];
        int r[4];
#pragma unroll
        for (int it = 0; it < 4; it++) {
            r[it] = rb + bb * 4 + it;
            int id = sidx[hc * 64 + r[it]];
            v[it] = *(const float4*)(kv + (long)id * 256 + base + 4 * lid);
        }
#pragma unroll
        for (int it = 0; it < 4; it++) {
            uint32_t H01, L01, H23, L23;
            sp2(v[it].x, v[it].y, H01, L01);
            sp2(v[it].z, v[it].w, H23, L23);
            uint32_t o = r[it] * 256 + (((lid >> 1) ^ (r[it] & 7)) << 4) + ((lid & 1) << 3);
            *(uint2*)(smem + KBH(buf) + o) = make_uint2(H01, H23);
            *(uint2*)(smem + KBL(buf) + o) = make_uint2(L01, L23);
        }
    }
}

// consumer Phase A: 64-row half-chunk, warp tile M16 x N32
static __device__ __forceinline__ void mma_A(
    uint32_t sb, int buf, float* scc, int cw, int l15, int lh) {
    const int arow = cw * 16 + l15;
    const int qrow0 = l15, qrow1 = 16 + l15;
#pragma unroll
    for (int s = 0; s < 8; s++) {
        int ch = 2 * s + lh;
        uint32_t ao = arow * 256 + ((ch ^ (arow & 7)) << 4);
        uint32_t q0 = qrow0 * 256 + ((ch ^ (qrow0 & 7)) << 4);
        uint32_t q1 = qrow1 * 256 + ((ch ^ (qrow1 & 7)) << 4);
        uint32_t aH[4], aL[4], bH0[4], bH1[4], bL0[4], bL1[4];
        ldm4(aH, sb + KBH(buf) + ao);
        ldm4(aL, sb + KBL(buf) + ao);
        ldm4(bH0, sb + QT_H + q0);
        ldm4(bH1, sb + QT_H + q1);
        ldm4(bL0, sb + QT_L + q0);
        ldm4(bL1, sb + QT_L + q1);
        mma16816(scc + 0,  aH, bH0[0], bH0[2]);
        mma16816(scc + 4,  aH, bH0[1], bH0[3]);
        mma16816(scc + 8,  aH, bH1[0], bH1[2]);
        mma16816(scc + 12, aH, bH1[1], bH1[3]);
        mma16816(scc + 0,  aH, bL0[0], bL0[2]);
        mma16816(scc + 4,  aH, bL0[1], bL0[3]);
        mma16816(scc + 8,  aH, bL1[0], bL1[2]);
        mma16816(scc + 12, aH, bL1[1], bL1[3]);
        mma16816(scc + 0,  aL, bH0[0], bH0[2]);
        mma16816(scc + 4,  aL, bH0[1], bH0[3]);
        mma16816(scc + 8,  aL, bH1[0], bH1[2]);
        mma16816(scc + 12, aL, bH1[1], bH1[3]);
    }
}

// consumer Phase C: 64 V-rows in buf (global half hcl), warp tile M32h x N32d
static __device__ __forceinline__ void mma_C(
    uint32_t sb, int buf, int hcl, float* oacc, int cw, int l15, int lh, int lid) {
    const int kl = (lid & 7) + ((lid >> 4) << 3);
    const int hcL = (lid >> 3) & 1;
#pragma unroll
    for (int s = 0; s < 4; s++) {
        int kb = hcl * 64 + s * 16;
        int kk = kb + kl;
        uint32_t adr0 = poff(kk, hcL);
        uint32_t adr1 = poff(kk, 2 + hcL);
        uint32_t aH0[4], aH1[4], aL0[4], aL1[4];
        ldm4t(aH0, sb + P_HI + adr0);
        ldm4t(aH1, sb + P_HI + adr1);
        ldm4t(aL0, sb + P_LO + adr0);
        ldm4t(aL1, sb + P_LO + adr1);
        int vrow = s * 16 + l15;
        uint32_t vc0 = cw * 4 + lh, vc1 = vc0 + 2;
        uint32_t v0 = vrow * 256 + ((vc0 ^ (vrow & 7)) << 4);
        uint32_t v1 = vrow * 256 + ((vc1 ^ (vrow & 7)) << 4);
        uint32_t vH0[4], vH1[4], vL0[4], vL1[4];
        ldm4t(vH0, sb + KBH(buf) + v0);
        ldm4t(vH1, sb + KBH(buf) + v1);
        ldm4t(vL0, sb + KBL(buf) + v0);
        ldm4t(vL1, sb + KBL(buf) + v1);
        mma16816(oacc + 0,  aH0, vH0[0], vH0[1]);
        mma16816(oacc + 4,  aH0, vH0[2], vH0[3]);
        mma16816(oacc + 8,  aH0, vH1[0], vH1[1]);
        mma16816(oacc + 12, aH0, vH1[2], vH1[3]);
        mma16816(oacc + 16, aH1, vH0[0], vH0[1]);
        mma16816(oacc + 20, aH1, vH0[2], vH0[3]);
        mma16816(oacc + 24, aH1, vH1[0], vH1[1]);
        mma16816(oacc + 28, aH1, vH1[2], vH1[3]);
        mma16816(oacc + 0,  aH0, vL0[0], vL0[1]);
        mma16816(oacc + 4,  aH0, vL0[2], vL0[3]);
        mma16816(oacc + 8,  aH0, vL1[0], vL1[1]);
        mma16816(oacc + 12, aH0, vL1[2], vL1[3]);
        mma16816(oacc + 16, aH1, vL0[0], vL0[1]);
        mma16816(oacc + 20, aH1, vL0[2], vL0[3]);
        mma16816(oacc + 24, aH1, vL1[0], vL1[1]);
        mma16816(oacc + 28, aH1, vL1[2], vL1[3]);
        mma16816(oacc + 0,  aL0, vH0[0], vH0[1]);
        mma16816(oacc + 4,  aL0, vH0[2], vH0[3]);
        mma16816(oacc + 8,  aL0, vH1[0], vH1[1]);
        mma16816(oacc + 12, aL0, vH1[2], vH1[3]);
        mma16816(oacc + 16, aL1, vH0[0], vH0[1]);
        mma16816(oacc + 20, aL1, vH0[2], vH0[3]);
        mma16816(oacc + 24, aL1, vH1[0], vH1[1]);
        mma16816(oacc + 28, aL1, vH1[2], vH1[3]);
    }
}

__global__ void __launch_bounds__(256, 2)
sparse_attn_v9(const float* __restrict__ q, const float* __restrict__ kv,
               const float* __restrict__ sink, const int* __restrict__ topk,
               float* __restrict__ out) {
    extern __shared__ __align__(1024) unsigned char smem[];
    const uint32_t sb = smem_u32(smem);
    const int tid = threadIdx.x, wid = tid >> 5, lid = tid & 31;
    const int l15 = lid & 15, lh = lid >> 4;
    const int pt = tid & 127;
    const int cw = wid & 3;
    const bool cons = wid < 4;
    const int sq = blockIdx.x;
    float* redm = (float*)(smem + REDM);
    float* reds = (float*)(smem + REDS);
    float* invv = (float*)(smem + INVV);
    int*   sidx = (int*)(smem + SIDX);

    float sc[64];
    float oacc[32];

    // ---- s0: consumers convert Q (8 rows/warp, row-contiguous); producers idx + K half0 ----
    if (cons) {
        const float* qg = q + (long)sq * 4096;
#pragma unroll
        for (int bb = 0; bb < 2; bb++) {
            float4 v[4];
            int r[4];
#pragma unroll
            for (int it = 0; it < 4; it++) {
                r[it] = cw * 8 + bb * 4 + it;
                v[it] = *(const float4*)(qg + r[it] * 128 + 4 * lid);
            }
#pragma unroll
            for (int it = 0; it < 4; it++) {
                uint32_t H01, L01, H23, L23;
                sp2(v[it].x * SCALE_F, v[it].y * SCALE_F, H01, L01);
                sp2(v[it].z * SCALE_F, v[it].w * SCALE_F, H23, L23);
                uint32_t o = r[it] * 256 + (((lid >> 1) ^ (r[it] & 7)) << 4) + ((lid & 1) << 3);
                *(uint2*)(smem + QT_H + o) = make_uint2(H01, H23);
                *(uint2*)(smem + QT_L + o) = make_uint2(L01, L23);
            }
        }
#pragma unroll
        for (int t = 0; t < 64; t++) sc[t] = 0.f;
    } else {
        sidx[pt]       = __ldg(topk + (long)sq * 256 + pt);
        sidx[pt + 128] = __ldg(topk + (long)sq * 256 + 128 + pt);
        asm volatile("bar.sync 2, 128;" ::: "memory");
        prod_half(smem, kv, sidx, 0, 0, 0, wid - 4, lid);
    }
    __syncthreads();

    // ---- s1-s4: Phase A MMA pipeline ----
    if (cons) mma_A(sb, 0, sc + 0, cw, l15, lh);
    else      prod_half(smem, kv, sidx, 0, 1, 1, wid - 4, lid);
    __syncthreads();
    if (cons) mma_A(sb, 1, sc + 16, cw, l15, lh);
    else      prod_half(smem, kv, sidx, 0, 2, 0, wid - 4, lid);
    __syncthreads();
    if (cons) mma_A(sb, 0, sc + 32, cw, l15, lh);
    else      prod_half(smem, kv, sidx, 0, 3, 1, wid - 4, lid);
    __syncthreads();
    if (cons) mma_A(sb, 1, sc + 48, cw, l15, lh);
    else      prod_half(smem, kv, sidx, 128, 0, 0, wid - 4, lid);   // V half0 -> b0
    __syncthreads();

    // ---- s5: consumers softmax -> k-major P; producers V half1 ----
    if (cons) {
        float mx[8];
#pragma unroll
        for (int jj = 0; jj < 8; jj++) mx[jj] = -1e30f;
#pragma unroll
        for (int t = 0; t < 2; t++)
#pragma unroll
            for (int j = 0; j < 4; j++) {
                float* f = sc + 16 * (2 * t) + 4 * j;
                float* g = sc + 16 * (2 * t + 1) + 4 * j;
                mx[2 * j + 0] = fmaxf(mx[2 * j + 0],
                                      fmaxf(fmaxf(f[0], f[2]), fmaxf(g[0], g[2])));
                mx[2 * j + 1] = fmaxf(mx[2 * j + 1],
                                      fmaxf(fmaxf(f[1], f[3]), fmaxf(g[1], g[3])));
            }
#pragma unroll
        for (int off = 4; off < 32; off <<= 1)
#pragma unroll
            for (int jj = 0; jj < 8; jj++)
                mx[jj] = fmaxf(mx[jj], __shfl_xor_sync(0xffffffffu, mx[jj], off));
        if (lid < 4) {
#pragma unroll
            for (int jj = 0; jj < 8; jj++)
                redm[cw * 32 + 8 * (jj >> 1) + 2 * lid + (jj & 1)] = mx[jj];
        }
        asm volatile("bar.sync 1, 128;" ::: "memory");
        float mfin[8];
#pragma unroll
        for (int jj = 0; jj < 8; jj++) {
            int h = 8 * (jj >> 1) + 2 * (lid & 3) + (jj & 1);
            float m = __ldg(sink + h);
#pragma unroll
            for (int w = 0; w < 4; w++) m = fmaxf(m, redm[w * 32 + h]);
            mfin[jj] = m;
        }
        float sm[8];
#pragma unroll
        for (int jj = 0; jj < 8; jj++) sm[jj] = 0.f;
#pragma unroll
        for (int hc = 0; hc < 4; hc++)
#pragma unroll
            for (int j = 0; j < 4; j++) {
                int kb = hc * 64 + cw * 16 + (lid >> 2);
                float e0 = __expf(sc[hc * 16 + 4 * j + 0] - mfin[2 * j + 0]);
                float e1 = __expf(sc[hc * 16 + 4 * j + 1] - mfin[2 * j + 1]);
                float e2 = __expf(sc[hc * 16 + 4 * j + 2] - mfin[2 * j + 0]);
                float e3 = __expf(sc[hc * 16 + 4 * j + 3] - mfin[2 * j + 1]);
                sm[2 * j + 0] += e0 + e2;
                sm[2 * j + 1] += e1 + e3;
                uint32_t H01, L01, H23, L23;
                sp2(e0, e1, H01, L01);
                sp2(e2, e3, H23, L23);
                uint32_t o0 = poff(kb, j) + 4 * (lid & 3);
                uint32_t o2 = poff(kb + 8, j) + 4 * (lid & 3);
                *(uint32_t*)(smem + P_HI + o0) = H01;
                *(uint32_t*)(smem + P_LO + o0) = L01;
                *(uint32_t*)(smem + P_HI + o2) = H23;
                *(uint32_t*)(smem + P_LO + o2) = L23;
            }
#pragma unroll
        for (int off = 4; off < 32; off <<= 1)
#pragma unroll
            for (int jj = 0; jj < 8; jj++)
                sm[jj] += __shfl_xor_sync(0xffffffffu, sm[jj], off);
        if (lid < 4) {
#pragma unroll
            for (int jj = 0; jj < 8; jj++)
                reds[cw * 32 + 8 * (jj >> 1) + 2 * lid + (jj & 1)] = sm[jj];
        }
        asm volatile("bar.sync 1, 128;" ::: "memory");
        if (cw == 0) {
            int h = lid;
            float sk = __ldg(sink + h);
            float m = sk;
#pragma unroll
            for (int w = 0; w < 4; w++) m = fmaxf(m, redm[w * 32 + h]);
            float den = __expf(sk - m);
#pragma unroll
            for (int w = 0; w < 4; w++) den += reds[w * 32 + h];
            invv[h] = 1.f / den;
        }
#pragma unroll
        for (int t = 0; t < 32; t++) oacc[t] = 0.f;
    } else {
        prod_half(smem, kv, sidx, 128, 1, 1, wid - 4, lid);   // V half1 -> b1
    }
    __syncthreads();

    // ---- s6-s9: Phase C MMA pipeline ----
    if (cons) mma_C(sb, 0, 0, oacc, cw, l15, lh, lid);
    __syncthreads();
    if (cons) mma_C(sb, 1, 1, oacc, cw, l15, lh, lid);
    else      prod_half(smem, kv, sidx, 128, 2, 0, wid - 4, lid);   // V half2 -> b0
    __syncthreads();
    if (cons) mma_C(sb, 0, 2, oacc, cw, l15, lh, lid);
    else      prod_half(smem, kv, sidx, 128, 3, 1, wid - 4, lid);   // V half3 -> b1
    __syncthreads();
    if (cons) {
        mma_C(sb, 1, 3, oacc, cw, l15, lh, lid);
        float* op = out + (long)sq * 4096;
#pragma unroll
        for (int i = 0; i < 2; i++) {
            int h0 = 16 * i + (lid >> 2);
            float iv0 = invv[h0], iv1 = invv[h0 + 8];
#pragma unroll
            for (int j = 0; j < 4; j++) {
                int d = cw * 32 + 8 * j + 2 * (lid & 3);
                float* b = oacc + i * 16 + j * 4;
                *(float2*)(op + h0 * 128 + d) = make_float2(b[0] * iv0, b[1] * iv0);
                *(float2*)(op + (h0 + 8) * 128 + d) = make_float2(b[2] * iv1, b[3] * iv1);
            }
        }
    }
}

extern "C" void kernel_launch(void* const* d_in, const int* in_sizes, int n_in,
                              void* d_out, int out_size) {
    (void)in_sizes; (void)n_in; (void)out_size;
    const float* q    = (const float*)d_in[0];
    const float* kv   = (const float*)d_in[1];
    const float* sink = (const float*)d_in[2];
    const int*   topk = (const int*)d_in[3];
    float* out = (float*)d_out;

    cudaFuncSetAttribute(sparse_attn_v9,
                         cudaFuncAttributeMaxDynamicSharedMemorySize, SMEM_BYTES);
    sparse_attn_v9<<<2048, 256, SMEM_BYTES>>>(q, kv, sink, topk, out);
}

// round 10
// speedup vs baseline: 1.4816x; 1.1274x over previous
#include <cuda_runtime.h>
#include <cstdint>

#define SCALE_F 0.08838834764831845f

// persistent split-bf16 KV tables (4096 rows x 256 elems), filled per launch
__device__ uint16_t g_kvh[4096 * 256];
__device__ uint16_t g_kvl[4096 * 256];

// ---------------- smem byte offsets ----------------
#define KBH(b) ((b) * 32768)
#define KBL(b) ((b) * 32768 + 16384)
#define QT_H   65536     // Q hi: 32 rows x 256B
#define QT_L   73728     // Q lo
#define P_LO   65536     // P lo aliases QT (Q dead by softmax); 256 k x 64B
#define P_HI   81920     // P hi: 256 k x 64B
#define REDM   98304
#define REDS   98816
#define INVV   99328
#define SIDX   99456
#define SMEM_BYTES 100480

// ---------------- helpers ----------------
static __device__ __forceinline__ uint32_t smem_u32(const void* p) {
    uint32_t a;
    asm("{ .reg .u64 t; cvta.to.shared.u64 t, %1; cvt.u32.u64 %0, t; }" : "=r"(a) : "l"(p));
    return a;
}
static __device__ __forceinline__ void ldm4(uint32_t* r, uint32_t addr) {
    asm volatile("ldmatrix.sync.aligned.m8n8.x4.shared.b16 {%0,%1,%2,%3}, [%4];"
                 : "=r"(r[0]), "=r"(r[1]), "=r"(r[2]), "=r"(r[3]) : "r"(addr));
}
static __device__ __forceinline__ void ldm4t(uint32_t* r, uint32_t addr) {
    asm volatile("ldmatrix.sync.aligned.m8n8.x4.trans.shared.b16 {%0,%1,%2,%3}, [%4];"
                 : "=r"(r[0]), "=r"(r[1]), "=r"(r[2]), "=r"(r[3]) : "r"(addr));
}
static __device__ __forceinline__ void mma16816(float* c, const uint32_t* a,
                                                uint32_t b0, uint32_t b1) {
    asm volatile("mma.sync.aligned.m16n8k16.row.col.f32.bf16.bf16.f32 "
                 "{%0,%1,%2,%3}, {%4,%5,%6,%7}, {%8,%9}, {%0,%1,%2,%3};"
                 : "+f"(c[0]), "+f"(c[1]), "+f"(c[2]), "+f"(c[3])
                 : "r"(a[0]), "r"(a[1]), "r"(a[2]), "r"(a[3]), "r"(b0), "r"(b1));
}
// pair split: H = packed (bf16t(x0), bf16t(x1)); L = packed rn-residuals
static __device__ __forceinline__ void sp2(float x0, float x1, uint32_t& H, uint32_t& L) {
    unsigned u0 = __float_as_uint(x0), u1 = __float_as_uint(x1);
    asm("prmt.b32 %0, %1, %2, 0x7632;" : "=r"(H) : "r"(u0), "r"(u1));
    float r0 = x0 - __uint_as_float(u0 & 0xFFFF0000u);
    float r1 = x1 - __uint_as_float(u1 & 0xFFFF0000u);
    asm("cvt.rn.bf16x2.f32 %0, %1, %2;" : "=r"(L) : "f"(r1), "f"(r0));
}
// k-major P byte offset for (k, h-chunk hc in 0..3): row 64B, XOR swizzle
static __device__ __forceinline__ uint32_t poff(int k, int hc) {
    return (uint32_t)(k * 64 + ((hc ^ ((k >> 1) & 3)) << 4));
}

// ---- pre-kernel: split-convert the whole KV table once ----
__global__ void __launch_bounds__(256) cvt_kv_kernel(const float* __restrict__ kv) {
    int t = blockIdx.x * 256 + threadIdx.x;     // 262144 threads x 4 elems
    float4 v = *(const float4*)(kv + (long)t * 4);
    uint32_t H01, L01, H23, L23;
    sp2(v.x, v.y, H01, L01);
    sp2(v.z, v.w, H23, L23);
    *(uint2*)((char*)g_kvh + (long)t * 8) = make_uint2(H01, H23);
    *(uint2*)((char*)g_kvl + (long)t * 8) = make_uint2(L01, L23);
}

// producer: pure cp.async gather of one 64-row half into buffer buf.
// lanes 0-15 stream the hi row (16B each), lanes 16-31 the lo row.
static __device__ __forceinline__ void prod_half(
    uint32_t sb, const int* sidx, int base /*bytes: 0=K, 256=V*/,
    int hc, int buf, int wloc, int lid) {
    const int half = lid >> 4;          // 0: hi table, 1: lo table
    const int c = lid & 15;             // 16B chunk within row
    const uint16_t* tbl = half ? g_kvl : g_kvh;
    const uint32_t dstbase = sb + (half ? KBL(buf) : KBH(buf));
#pragma unroll
    for (int it = 0; it < 16; it++) {
        int r = wloc * 16 + it;
        int id = sidx[hc * 64 + r];
        const char* src = (const char*)tbl + (long)id * 512 + base + c * 16;
        uint32_t dst = dstbase + r * 256 + ((c ^ (r & 7)) << 4);
        asm volatile("cp.async.cg.shared.global [%0], [%1], 16;"
                     :: "r"(dst), "l"(__cvta_generic_to_global(src)));
    }
    asm volatile("cp.async.commit_group;");
    asm volatile("cp.async.wait_group 0;" ::: "memory");
}

// consumer Phase A: 64-row half-chunk, warp tile M16 x N32
static __device__ __forceinline__ void mma_A(
    uint32_t sb, int buf, float* scc, int cw, int l15, int lh) {
    const int arow = cw * 16 + l15;
    const int qrow0 = l15, qrow1 = 16 + l15;
#pragma unroll
    for (int s = 0; s < 8; s++) {
        int ch = 2 * s + lh;
        uint32_t ao = arow * 256 + ((ch ^ (arow & 7)) << 4);
        uint32_t q0 = qrow0 * 256 + ((ch ^ (qrow0 & 7)) << 4);
        uint32_t q1 = qrow1 * 256 + ((ch ^ (qrow1 & 7)) << 4);
        uint32_t aH[4], aL[4], bH0[4], bH1[4], bL0[4], bL1[4];
        ldm4(aH, sb + KBH(buf) + ao);
        ldm4(aL, sb + KBL(buf) + ao);
        ldm4(bH0, sb + QT_H + q0);
        ldm4(bH1, sb + QT_H + q1);
        ldm4(bL0, sb + QT_L + q0);
        ldm4(bL1, sb + QT_L + q1);
        mma16816(scc + 0,  aH, bH0[0], bH0[2]);
        mma16816(scc + 4,  aH, bH0[1], bH0[3]);
        mma16816(scc + 8,  aH, bH1[0], bH1[2]);
        mma16816(scc + 12, aH, bH1[1], bH1[3]);
        mma16816(scc + 0,  aH, bL0[0], bL0[2]);
        mma16816(scc + 4,  aH, bL0[1], bL0[3]);
        mma16816(scc + 8,  aH, bL1[0], bL1[2]);
        mma16816(scc + 12, aH, bL1[1], bL1[3]);
        mma16816(scc + 0,  aL, bH0[0], bH0[2]);
        mma16816(scc + 4,  aL, bH0[1], bH0[3]);
        mma16816(scc + 8,  aL, bH1[0], bH1[2]);
        mma16816(scc + 12, aL, bH1[1], bH1[3]);
    }
}

// consumer Phase C: 64 V-rows in buf (global half hcl), warp tile M32h x N32d
static __device__ __forceinline__ void mma_C(
    uint32_t sb, int buf, int hcl, float* oacc, int cw, int l15, int lh, int lid) {
    const int kl = (lid & 7) + ((lid >> 4) << 3);
    const int hcL = (lid >> 3) & 1;
#pragma unroll
    for (int s = 0; s < 4; s++) {
        int kb = hcl * 64 + s * 16;
        int kk = kb + kl;
        uint32_t adr0 = poff(kk, hcL);
        uint32_t adr1 = poff(kk, 2 + hcL);
        uint32_t aH0[4], aH1[4], aL0[4], aL1[4];
        ldm4t(aH0, sb + P_HI + adr0);
        ldm4t(aH1, sb + P_HI + adr1);
        ldm4t(aL0, sb + P_LO + adr0);
        ldm4t(aL1, sb + P_LO + adr1);
        int vrow = s * 16 + l15;
        uint32_t vc0 = cw * 4 + lh, vc1 = vc0 + 2;
        uint32_t v0 = vrow * 256 + ((vc0 ^ (vrow & 7)) << 4);
        uint32_t v1 = vrow * 256 + ((vc1 ^ (vrow & 7)) << 4);
        uint32_t vH0[4], vH1[4], vL0[4], vL1[4];
        ldm4t(vH0, sb + KBH(buf) + v0);
        ldm4t(vH1, sb + KBH(buf) + v1);
        ldm4t(vL0, sb + KBL(buf) + v0);
        ldm4t(vL1, sb + KBL(buf) + v1);
        mma16816(oacc + 0,  aH0, vH0[0], vH0[1]);
        mma16816(oacc + 4,  aH0, vH0[2], vH0[3]);
        mma16816(oacc + 8,  aH0, vH1[0], vH1[1]);
        mma16816(oacc + 12, aH0, vH1[2], vH1[3]);
        mma16816(oacc + 16, aH1, vH0[0], vH0[1]);
        mma16816(oacc + 20, aH1, vH0[2], vH0[3]);
        mma16816(oacc + 24, aH1, vH1[0], vH1[1]);
        mma16816(oacc + 28, aH1, vH1[2], vH1[3]);
        mma16816(oacc + 0,  aH0, vL0[0], vL0[1]);
        mma16816(oacc + 4,  aH0, vL0[2], vL0[3]);
        mma16816(oacc + 8,  aH0, vL1[0], vL1[1]);
        mma16816(oacc + 12, aH0, vL1[2], vL1[3]);
        mma16816(oacc + 16, aH1, vL0[0], vL0[1]);
        mma16816(oacc + 20, aH1, vL0[2], vL0[3]);
        mma16816(oacc + 24, aH1, vL1[0], vL1[1]);
        mma16816(oacc + 28, aH1, vL1[2], vL1[3]);
        mma16816(oacc + 0,  aL0, vH0[0], vH0[1]);
        mma16816(oacc + 4,  aL0, vH0[2], vH0[3]);
        mma16816(oacc + 8,  aL0, vH1[0], vH1[1]);
        mma16816(oacc + 12, aL0, vH1[2], vH1[3]);
        mma16816(oacc + 16, aL1, vH0[0], vH0[1]);
        mma16816(oacc + 20, aL1, vH0[2], vH0[3]);
        mma16816(oacc + 24, aL1, vH1[0], vH1[1]);
        mma16816(oacc + 28, aL1, vH1[2], vH1[3]);
    }
}

__global__ void __launch_bounds__(256, 2)
sparse_attn_v10(const float* __restrict__ q,
                const float* __restrict__ sink, const int* __restrict__ topk,
                float* __restrict__ out) {
    extern __shared__ __align__(1024) unsigned char smem[];
    const uint32_t sb = smem_u32(smem);
    const int tid = threadIdx.x, wid = tid >> 5, lid = tid & 31;
    const int l15 = lid & 15, lh = lid >> 4;
    const int pt = tid & 127;
    const int cw = wid & 3;
    const bool cons = wid < 4;
    const int sq = blockIdx.x;
    float* redm = (float*)(smem + REDM);
    float* reds = (float*)(smem + REDS);
    float* invv = (float*)(smem + INVV);
    int*   sidx = (int*)(smem + SIDX);

    float sc[64];
    float oacc[32];

    // ---- s0: consumers convert Q; producers cache indices + K half0 ----
    if (cons) {
        const float* qg = q + (long)sq * 4096;
#pragma unroll
        for (int bb = 0; bb < 2; bb++) {
            float4 v[4];
            int r[4];
#pragma unroll
            for (int it = 0; it < 4; it++) {
                r[it] = cw * 8 + bb * 4 + it;
                v[it] = *(const float4*)(qg + r[it] * 128 + 4 * lid);
            }
#pragma unroll
            for (int it = 0; it < 4; it++) {
                uint32_t H01, L01, H23, L23;
                sp2(v[it].x * SCALE_F, v[it].y * SCALE_F, H01, L01);
                sp2(v[it].z * SCALE_F, v[it].w * SCALE_F, H23, L23);
                uint32_t o = r[it] * 256 + (((lid >> 1) ^ (r[it] & 7)) << 4) + ((lid & 1) << 3);
                *(uint2*)(smem + QT_H + o) = make_uint2(H01, H23);
                *(uint2*)(smem + QT_L + o) = make_uint2(L01, L23);
            }
        }
#pragma unroll
        for (int t = 0; t < 64; t++) sc[t] = 0.f;
    } else {
        sidx[pt]       = __ldg(topk + (long)sq * 256 + pt);
        sidx[pt + 128] = __ldg(topk + (long)sq * 256 + 128 + pt);
        asm volatile("bar.sync 2, 128;" ::: "memory");
        prod_half(sb, sidx, 0, 0, 0, wid - 4, lid);
    }
    __syncthreads();

    // ---- s1-s4: Phase A MMA pipeline ----
    if (cons) mma_A(sb, 0, sc + 0, cw, l15, lh);
    else      prod_half(sb, sidx, 0, 1, 1, wid - 4, lid);
    __syncthreads();
    if (cons) mma_A(sb, 1, sc + 16, cw, l15, lh);
    else      prod_half(sb, sidx, 0, 2, 0, wid - 4, lid);
    __syncthreads();
    if (cons) mma_A(sb, 0, sc + 32, cw, l15, lh);
    else      prod_half(sb, sidx, 0, 3, 1, wid - 4, lid);
    __syncthreads();
    if (cons) mma_A(sb, 1, sc + 48, cw, l15, lh);
    else      prod_half(sb, sidx, 256, 0, 0, wid - 4, lid);   // V half0 -> b0
    __syncthreads();

    // ---- s5: consumers softmax -> k-major P; producers V half1 ----
    if (cons) {
        float mx[8];
#pragma unroll
        for (int jj = 0; jj < 8; jj++) mx[jj] = -1e30f;
#pragma unroll
        for (int t = 0; t < 2; t++)
#pragma unroll
            for (int j = 0; j < 4; j++) {
                float* f = sc + 16 * (2 * t) + 4 * j;
                float* g = sc + 16 * (2 * t + 1) + 4 * j;
                mx[2 * j + 0] = fmaxf(mx[2 * j + 0],
                                      fmaxf(fmaxf(f[0], f[2]), fmaxf(g[0], g[2])));
                mx[2 * j + 1] = fmaxf(mx[2 * j + 1],
                                      fmaxf(fmaxf(f[1], f[3]), fmaxf(g[1], g[3])));
            }
#pragma unroll
        for (int off = 4; off < 32; off <<= 1)
#pragma unroll
            for (int jj = 0; jj < 8; jj++)
                mx[jj] = fmaxf(mx[jj], __shfl_xor_sync(0xffffffffu, mx[jj], off));
        if (lid < 4) {
#pragma unroll
            for (int jj = 0; jj < 8; jj++)
                redm[cw * 32 + 8 * (jj >> 1) + 2 * lid + (jj & 1)] = mx[jj];
        }
        asm volatile("bar.sync 1, 128;" ::: "memory");
        float mfin[8];
#pragma unroll
        for (int jj = 0; jj < 8; jj++) {
            int h = 8 * (jj >> 1) + 2 * (lid & 3) + (jj & 1);
            float m = __ldg(sink + h);
#pragma unroll
            for (int w = 0; w < 4; w++) m = fmaxf(m, redm[w * 32 + h]);
            mfin[jj] = m;
        }
        float sm[8];
#pragma unroll
        for (int jj = 0; jj < 8; jj++) sm[jj] = 0.f;
#pragma unroll
        for (int hc = 0; hc < 4; hc++)
#pragma unroll
            for (int j = 0; j < 4; j++) {
                int kb = hc * 64 + cw * 16 + (lid >> 2);
                float e0 = __expf(sc[hc * 16 + 4 * j + 0] - mfin[2 * j + 0]);
                float e1 = __expf(sc[hc * 16 + 4 * j + 1] - mfin[2 * j + 1]);
                float e2 = __expf(sc[hc * 16 + 4 * j + 2] - mfin[2 * j + 0]);
                float e3 = __expf(sc[hc * 16 + 4 * j + 3] - mfin[2 * j + 1]);
                sm[2 * j + 0] += e0 + e2;
                sm[2 * j + 1] += e1 + e3;
                uint32_t H01, L01, H23, L23;
                sp2(e0, e1, H01, L01);
                sp2(e2, e3, H23, L23);
                uint32_t o0 = poff(kb, j) + 4 * (lid & 3);
                uint32_t o2 = poff(kb + 8, j) + 4 * (lid & 3);
                *(uint32_t*)(smem + P_HI + o0) = H01;
                *(uint32_t*)(smem + P_LO + o0) = L01;
                *(uint32_t*)(smem + P_HI + o2) = H23;
                *(uint32_t*)(smem + P_LO + o2) = L23;
            }
#pragma unroll
        for (int off = 4; off < 32; off <<= 1)
#pragma unroll
            for (int jj = 0; jj < 8; jj++)
                sm[jj] += __shfl_xor_sync(0xffffffffu, sm[jj], off);
        if (lid < 4) {
#pragma unroll
            for (int jj = 0; jj < 8; jj++)
                reds[cw * 32 + 8 * (jj >> 1) + 2 * lid + (jj & 1)] = sm[jj];
        }
        asm volatile("bar.sync 1, 128;" ::: "memory");
        if (cw == 0) {
            int h = lid;
            float sk = __ldg(sink + h);
            float m = sk;
#pragma unroll
            for (int w = 0; w < 4; w++) m = fmaxf(m, redm[w * 32 + h]);
            float den = __expf(sk - m);
#pragma unroll
            for (int w = 0; w < 4; w++) den += reds[w * 32 + h];
            invv[h] = 1.f / den;
        }
#pragma unroll
        for (int t = 0; t < 32; t++) oacc[t] = 0.f;
    } else {
        prod_half(sb, sidx, 256, 1, 1, wid - 4, lid);   // V half1 -> b1
    }
    __syncthreads();

    // ---- s6-s9: Phase C MMA pipeline ----
    if (cons) mma_C(sb, 0, 0, oacc, cw, l15, lh, lid);
    __syncthreads();
    if (cons) mma_C(sb, 1, 1, oacc, cw, l15, lh, lid);
    else      prod_half(sb, sidx, 256, 2, 0, wid - 4, lid);   // V half2 -> b0
    __syncthreads();
    if (cons) mma_C(sb, 0, 2, oacc, cw, l15, lh, lid);
    else      prod_half(sb, sidx, 256, 3, 1, wid - 4, lid);   // V half3 -> b1
    __syncthreads();
    if (cons) {
        mma_C(sb, 1, 3, oacc, cw, l15, lh, lid);
        float* op = out + (long)sq * 4096;
#pragma unroll
        for (int i = 0; i < 2; i++) {
            int h0 = 16 * i + (lid >> 2);
            float iv0 = invv[h0], iv1 = invv[h0 + 8];
#pragma unroll
            for (int j = 0; j < 4; j++) {
                int d = cw * 32 + 8 * j + 2 * (lid & 3);
                float* b = oacc + i * 16 + j * 4;
                *(float2*)(op + h0 * 128 + d) = make_float2(b[0] * iv0, b[1] * iv0);
                *(float2*)(op + (h0 + 8) * 128 + d) = make_float2(b[2] * iv1, b[3] * iv1);
            }
        }
    }
}

extern "C" void kernel_launch(void* const* d_in, const int* in_sizes, int n_in,
                              void* d_out, int out_size) {
    (void)in_sizes; (void)n_in; (void)out_size;
    const float* q    = (const float*)d_in[0];
    const float* kv   = (const float*)d_in[1];
    const float* sink = (const float*)d_in[2];
    const int*   topk = (const int*)d_in[3];
    float* out = (float*)d_out;

    // pre-pass: split-convert the 4MB KV table once (1M elems, 262144 threads)
    cvt_kv_kernel<<<1024, 256>>>(kv);

    cudaFuncSetAttribute(sparse_attn_v10,
                         cudaFuncAttributeMaxDynamicSharedMemorySize, SMEM_BYTES);
    sparse_attn_v10<<<2048, 256, SMEM_BYTES>>>(q, sink, topk, out);
}